// round 5
// baseline (speedup 1.0000x reference)
#include <cuda_runtime.h>

#define PI_F 3.14159265358979323846f

// ---------------------------------------------------------------------------
// Fixed shapes:
//   features      [8192, 4096] f32
//   projection_w  [16, 4096]   f32
//   projection_b  [16]         f32
//   vqc_weights   [24, 16, 3]  f32
//   linear_w      [16, 512]    f32
//   linear_b      [512]        f32
//   out           [8192, 512]  f32
// ---------------------------------------------------------------------------
constexpr int B_ROWS  = 8192;
constexpr int D_DIM   = 4096;
constexpr int Q_DIM   = 16;
constexpr int L_LAY   = 24;
constexpr int C_DIM   = 512;

constexpr int ROWS_PER_BLOCK = 32;
constexpr int THREADS        = 256;   // 16 row-groups x 16 k-slices, 2 rows each
constexpr int NUM_BLOCKS     = B_ROWS / ROWS_PER_BLOCK;   // 256

// dynamic smem (floats):
//   scratch: 512 states x 16 k-slices = 8192 floats (32 KB), reused as zbuf
//   trig:    24*16*6 = 2304 floats (9 KB)
// total 41984 B < 48 KB default -> no cudaFuncSetAttribute needed.
constexpr int SCRATCH_FLOATS = ROWS_PER_BLOCK * Q_DIM * 16;     // 8192
constexpr int TRIG_FLOATS    = L_LAY * Q_DIM * 6;               // 2304
constexpr int SMEM_BYTES     = (SCRATCH_FLOATS + TRIG_FLOATS) * 4;

// ---- packed fp32x2 helpers (B300 double-rate fp32 path) -------------------
__device__ __forceinline__ unsigned long long ffma2(unsigned long long a,
                                                    unsigned long long b,
                                                    unsigned long long c) {
    unsigned long long d;
    asm("fma.rn.f32x2 %0, %1, %2, %3;" : "=l"(d) : "l"(a), "l"(b), "l"(c));
    return d;
}
__device__ __forceinline__ float f2lo(unsigned long long v) {
    return __uint_as_float((unsigned)(v & 0xffffffffull));
}
__device__ __forceinline__ float f2hi(unsigned long long v) {
    return __uint_as_float((unsigned)(v >> 32));
}
__device__ __forceinline__ unsigned long long packf2(float lo, float hi) {
    unsigned long long d;
    asm("mov.b64 %0, {%1, %2};" : "=l"(d)
        : "r"(__float_as_uint(lo)), "r"(__float_as_uint(hi)));
    return d;
}

__global__ void __launch_bounds__(THREADS, 2)
vqc_router_fused(const float* __restrict__ features,
                 const float* __restrict__ pw,
                 const float* __restrict__ pb,
                 const float* __restrict__ vqcw,
                 const float* __restrict__ lw,
                 const float* __restrict__ lb,
                 float* __restrict__ out)
{
    extern __shared__ float smem[];
    float* scratch = smem;                    // 8192 floats (reused as zbuf)
    float* trig    = smem + SCRATCH_FLOATS;   // 2304 floats

    const int tid  = threadIdx.x;
    const int lane = tid & 31;
    const int warp = tid >> 5;                // 0..7
    const int s    = lane & 15;               // k-slice id within 64-k span
    const int rg   = warp * 2 + (lane >> 4);  // row-group 0..15 (2 rows each)
    const int row0 = blockIdx.x * ROWS_PER_BLOCK + rg * 2;

    // ---- precompute trig of VQC weights: [l][q][6] = cp,sp,ct,st,co,so ----
    for (int i = tid; i < L_LAY * Q_DIM * 3; i += THREADS) {
        float sv, cv;
        sincosf(vqcw[i], &sv, &cv);
        int l   = i / (Q_DIM * 3);
        int rem = i - l * (Q_DIM * 3);
        int q   = rem / 3;
        int p   = rem - q * 3;
        trig[(l * Q_DIM + q) * 6 + 2 * p + 0] = cv;
        trig[(l * Q_DIM + q) * 6 + 2 * p + 1] = sv;
    }

    // ---- GEMM1: 2 rows x 16 q per thread, 16-way k-split within half-warp -
    // thread's k set: { span*64 + 4*s .. +3 } for span = 0..63
    unsigned long long acc[2][16];
#pragma unroll
    for (int r = 0; r < 2; r++)
#pragma unroll
        for (int q = 0; q < 16; q++) acc[r][q] = 0ull;

    const float* fb = features + (size_t)row0 * D_DIM + s * 4;
    const float* wb = pw + s * 4;

    // distance-2 feature prefetch: f0 = span sp, f1 = sp+1, fload -> sp+2
    ulonglong2 f0[2], f1[2];
#pragma unroll
    for (int r = 0; r < 2; r++) {
        f0[r] = *reinterpret_cast<const ulonglong2*>(fb + (size_t)r * D_DIM);
        f1[r] = *reinterpret_cast<const ulonglong2*>(fb + (size_t)r * D_DIM + 64);
    }

    for (int sp = 0; sp < 64; sp++) {
        const int koff = sp * 64;
        ulonglong2 f2[2];
        if (sp + 2 < 64) {
#pragma unroll
            for (int r = 0; r < 2; r++)
                f2[r] = *reinterpret_cast<const ulonglong2*>(
                    fb + (size_t)r * D_DIM + koff + 128);
        }
#pragma unroll
        for (int q = 0; q < 16; q++) {
            ulonglong2 wv = *reinterpret_cast<const ulonglong2*>(
                wb + (size_t)q * D_DIM + koff);
#pragma unroll
            for (int r = 0; r < 2; r++) {
                acc[r][q] = ffma2(f0[r].x, wv.x, acc[r][q]);
                acc[r][q] = ffma2(f0[r].y, wv.y, acc[r][q]);
            }
        }
#pragma unroll
        for (int r = 0; r < 2; r++) { f0[r] = f1[r]; f1[r] = f2[r]; }
    }

    // ---- write k-split partials: scratch[state][s], state = row_local*16+q
#pragma unroll
    for (int j = 0; j < 2; j++)
#pragma unroll
        for (int q = 0; q < 16; q++)
            scratch[((rg * 2 + j) * Q_DIM + q) * 16 + s] =
                f2lo(acc[j][q]) + f2hi(acc[j][q]);

    __syncthreads();

    // ---- reduce 16 partials, tanh, VQC (2 states per thread) --------------
    float zout[2];
#pragma unroll
    for (int i = 0; i < 2; i++) {
        const int idx = tid * 2 + i;          // 0..511
        const int q   = idx & 15;
        const float4* p4 = reinterpret_cast<const float4*>(scratch + idx * 16);
        float4 a0 = p4[0], a1 = p4[1], a2 = p4[2], a3 = p4[3];
        float p = ((a0.x + a0.y) + (a0.z + a0.w))
                + ((a1.x + a1.y) + (a1.z + a1.w))
                + ((a2.x + a2.y) + (a2.z + a2.w))
                + ((a3.x + a3.y) + (a3.z + a3.w)) + pb[q];

        float ang = PI_F * tanhf(p);
        float x, z;
        sincosf(ang, &x, &z);                 // x = sin, z = cos
        float y = 0.0f;
#pragma unroll
        for (int l = 0; l < L_LAY; l++) {
            const float* t6 = trig + (l * Q_DIM + q) * 6;
            float cp = t6[0], spv = t6[1];
            float ct = t6[2], st  = t6[3];
            float co = t6[4], so  = t6[5];
            float x1 = x * cp - y * spv;
            float y1 = x * spv + y * cp;
            float x2 = x1 * ct + z * st;
            float z2 = -x1 * st + z * ct;
            x = x2 * co - y1 * so;
            y = x2 * so + y1 * co;
            z = z2;
        }
        zout[i] = z;
    }
    __syncthreads();                          // everyone done reading scratch

    // reuse scratch as zbuf[32][16]
#pragma unroll
    for (int i = 0; i < 2; i++) scratch[tid * 2 + i] = zout[i];
    __syncthreads();

    // ---- GEMM2: out[32][512] = z[32][16] @ lw[16][512] + lb ---------------
    const int c0 = tid * 2;                   // two output cols per thread
    unsigned long long wreg[16];
#pragma unroll
    for (int q = 0; q < 16; q++)
        wreg[q] = *reinterpret_cast<const unsigned long long*>(
            lw + (size_t)q * C_DIM + c0);
    const unsigned long long bias2 =
        *reinterpret_cast<const unsigned long long*>(lb + c0);

    float* obase = out + (size_t)(blockIdx.x * ROWS_PER_BLOCK) * C_DIM + c0;
    for (int r = 0; r < ROWS_PER_BLOCK; r++) {
        unsigned long long a = bias2;
#pragma unroll
        for (int q = 0; q < 16; q++) {
            float zv = scratch[r * Q_DIM + q];
            a = ffma2(packf2(zv, zv), wreg[q], a);
        }
        *reinterpret_cast<unsigned long long*>(obase + (size_t)r * C_DIM) = a;
    }
}

extern "C" void kernel_launch(void* const* d_in, const int* in_sizes, int n_in,
                              void* d_out, int out_size) {
    const float* features = (const float*)d_in[0];
    const float* pw       = (const float*)d_in[1];
    const float* pb       = (const float*)d_in[2];
    const float* vqcw     = (const float*)d_in[3];
    const float* lw       = (const float*)d_in[4];
    const float* lb       = (const float*)d_in[5];
    float* out            = (float*)d_out;

    vqc_router_fused<<<NUM_BLOCKS, THREADS, SMEM_BYTES>>>(
        features, pw, pb, vqcw, lw, lb, out);
}

// round 7
// speedup vs baseline: 1.9337x; 1.9337x over previous
#include <cuda_runtime.h>
#include <cstdint>

#define PI_F 3.14159265358979323846f

// ---------------------------------------------------------------------------
// Fixed shapes:
//   features      [8192, 4096] f32      projection_w  [16, 4096] f32
//   projection_b  [16]         f32      vqc_weights   [24, 16, 3] f32
//   linear_w      [16, 512]    f32      linear_b      [512] f32
//   out           [8192, 512]  f32
// ---------------------------------------------------------------------------
constexpr int B_ROWS  = 8192;
constexpr int D_DIM   = 4096;
constexpr int Q_DIM   = 16;
constexpr int L_LAY   = 24;
constexpr int C_DIM   = 512;

constexpr int ROWS_PER_BLOCK = 32;
constexpr int THREADS        = 128;                       // 4 warps
constexpr int NUM_BLOCKS     = B_ROWS / ROWS_PER_BLOCK;   // 256 -> 2 blocks/SM

constexpr int CHUNK_K = 128;                 // k per pipeline stage
constexpr int NCHUNK  = D_DIM / CHUNK_K;     // 32
constexpr int NSUB    = 4;                   // 32-k subspans per chunk

// smem: scratch region (8192 floats = 32 KB) doubles as the weight pipeline
// (2 stages x 16 q x 128 k = 4096 floats = 16 KB) during the main loop.
constexpr int SCRATCH_FLOATS = ROWS_PER_BLOCK * Q_DIM * 16;   // 8192
constexpr int TRIG_FLOATS    = L_LAY * Q_DIM * 6;             // 2304
constexpr int SMEM_BYTES     = (SCRATCH_FLOATS + TRIG_FLOATS) * 4;  // 41984
constexpr int WSTAGE_FLOATS  = Q_DIM * CHUNK_K;               // 2048 per stage

// ---- packed fp32x2 helpers (B300 double-rate fp32 path) -------------------
__device__ __forceinline__ unsigned long long ffma2(unsigned long long a,
                                                    unsigned long long b,
                                                    unsigned long long c) {
    unsigned long long d;
    asm("fma.rn.f32x2 %0, %1, %2, %3;" : "=l"(d) : "l"(a), "l"(b), "l"(c));
    return d;
}
__device__ __forceinline__ float f2lo(unsigned long long v) {
    return __uint_as_float((unsigned)(v & 0xffffffffull));
}
__device__ __forceinline__ float f2hi(unsigned long long v) {
    return __uint_as_float((unsigned)(v >> 32));
}
__device__ __forceinline__ unsigned long long packf2(float lo, float hi) {
    unsigned long long d;
    asm("mov.b64 %0, {%1, %2};" : "=l"(d)
        : "r"(__float_as_uint(lo)), "r"(__float_as_uint(hi)));
    return d;
}

__device__ __forceinline__ void cp_async16(unsigned int dst_smem,
                                           const void* src) {
    asm volatile("cp.async.cg.shared.global [%0], [%1], 16;"
                 :: "r"(dst_smem), "l"(src) : "memory");
}
__device__ __forceinline__ void cp_commit() {
    asm volatile("cp.async.commit_group;" ::: "memory");
}
__device__ __forceinline__ void cp_wait1() {
    asm volatile("cp.async.wait_group 1;" ::: "memory");
}
__device__ __forceinline__ void cp_wait0() {
    asm volatile("cp.async.wait_group 0;" ::: "memory");
}

__global__ void __launch_bounds__(THREADS, 2)
vqc_router_fused(const float* __restrict__ features,
                 const float* __restrict__ pw,
                 const float* __restrict__ pb,
                 const float* __restrict__ vqcw,
                 const float* __restrict__ lw,
                 const float* __restrict__ lb,
                 float* __restrict__ out)
{
    extern __shared__ float smem[];
    float* scratch = smem;                    // 8192 floats; wstage lives here
    float* trig    = smem + SCRATCH_FLOATS;   // 2304 floats

    const int tid  = threadIdx.x;
    const int lane = tid & 31;
    const int warp = tid >> 5;                // 0..3
    const int s    = lane & 15;               // k-pair slice within 32-k subspan
    const int rg   = warp * 2 + (lane >> 4);  // row-group 0..7 (4 rows each)
    const int row0 = blockIdx.x * ROWS_PER_BLOCK + rg * 4;

    const unsigned int ws_base =
        (unsigned int)__cvta_generic_to_shared(scratch);

    // ---- precompute trig of VQC weights: [l][q][6] = cp,sp,ct,st,co,so ----
    for (int i = tid; i < L_LAY * Q_DIM * 3; i += THREADS) {
        float sv, cv;
        sincosf(vqcw[i], &sv, &cv);
        int l   = i / (Q_DIM * 3);
        int rem = i - l * (Q_DIM * 3);
        int q   = rem / 3;
        int p   = rem - q * 3;
        trig[(l * Q_DIM + q) * 6 + 2 * p + 0] = cv;
        trig[(l * Q_DIM + q) * 6 + 2 * p + 1] = sv;
    }

    // ---- weight stage loader: chunk c -> stage st (8 KB, 4 cp.async/thread)
    auto stage_weights = [&](int c, int st) {
#pragma unroll
        for (int r4 = 0; r4 < 4; r4++) {
            int seg = tid + THREADS * r4;         // 0..511
            int q   = seg >> 5;                   // 32 segs of 16 B per q row
            int off = seg & 31;
            cp_async16(ws_base + (unsigned int)(st * WSTAGE_FLOATS
                                                + q * CHUNK_K + off * 4) * 4u,
                       pw + (size_t)q * D_DIM + c * CHUNK_K + off * 4);
        }
    };

    // ---- GEMM1 pipeline prologue -----------------------------------------
    stage_weights(0, 0); cp_commit();
    stage_weights(1, 1); cp_commit();

    const float* fb = features + (size_t)row0 * D_DIM + 2 * s;

    unsigned long long acc[4][16];
#pragma unroll
    for (int r = 0; r < 4; r++)
#pragma unroll
        for (int q = 0; q < 16; q++) acc[r][q] = 0ull;

    // feature regs for current chunk: [row][sub], one f32x2 (2 k) each
    unsigned long long fcur[4][NSUB], fnxt[4][NSUB];
#pragma unroll
    for (int r = 0; r < 4; r++)
#pragma unroll
        for (int sub = 0; sub < NSUB; sub++)
            fcur[r][sub] = *reinterpret_cast<const unsigned long long*>(
                fb + (size_t)r * D_DIM + sub * 32);

    // ---- main loop over 32 k-chunks --------------------------------------
    for (int c = 0; c < NCHUNK; c++) {
        // issue next chunk's feature loads first (front-batched MLP)
        if (c + 1 < NCHUNK) {
#pragma unroll
            for (int r = 0; r < 4; r++)
#pragma unroll
                for (int sub = 0; sub < NSUB; sub++)
                    fnxt[r][sub] = *reinterpret_cast<const unsigned long long*>(
                        fb + (size_t)r * D_DIM + (c + 1) * CHUNK_K + sub * 32);
        }

        cp_wait1();               // chunk c's weight stage complete
        __syncthreads();

        const float* wst = scratch + (c & 1) * WSTAGE_FLOATS;

#pragma unroll
        for (int sub = 0; sub < NSUB; sub++) {
            unsigned long long w[16];
#pragma unroll
            for (int q = 0; q < 16; q++)
                w[q] = *reinterpret_cast<const unsigned long long*>(
                    wst + q * CHUNK_K + sub * 32 + 2 * s);
#pragma unroll
            for (int q = 0; q < 16; q++)
#pragma unroll
                for (int r = 0; r < 4; r++)
                    acc[r][q] = ffma2(fcur[r][sub], w[q], acc[r][q]);
        }

        __syncthreads();          // stage (c&1) fully consumed by all warps

        if (c + 2 < NCHUNK) stage_weights(c + 2, c & 1);
        cp_commit();              // always commit -> uniform wait_group 1

#pragma unroll
        for (int r = 0; r < 4; r++)
#pragma unroll
            for (int sub = 0; sub < NSUB; sub++) fcur[r][sub] = fnxt[r][sub];
    }
    cp_wait0();
    __syncthreads();              // weight pipeline done; scratch reusable

    // ---- write k-split partials: scratch[state][s], state = row_local*16+q
#pragma unroll
    for (int j = 0; j < 4; j++)
#pragma unroll
        for (int q = 0; q < 16; q++)
            scratch[((rg * 4 + j) * Q_DIM + q) * 16 + s] =
                f2lo(acc[j][q]) + f2hi(acc[j][q]);

    __syncthreads();

    // ---- reduce 16 partials, tanh, VQC (4 states per thread) --------------
    float zout[4];
#pragma unroll
    for (int i = 0; i < 4; i++) {
        const int idx = tid * 4 + i;          // 0..511
        const int q   = idx & 15;
        const float4* p4 = reinterpret_cast<const float4*>(scratch + idx * 16);
        float4 a0 = p4[0], a1 = p4[1], a2 = p4[2], a3 = p4[3];
        float p = ((a0.x + a0.y) + (a0.z + a0.w))
                + ((a1.x + a1.y) + (a1.z + a1.w))
                + ((a2.x + a2.y) + (a2.z + a2.w))
                + ((a3.x + a3.y) + (a3.z + a3.w)) + pb[q];

        float ang = PI_F * tanhf(p);
        float x, z;
        sincosf(ang, &x, &z);                 // x = sin, z = cos
        float y = 0.0f;
#pragma unroll
        for (int l = 0; l < L_LAY; l++) {
            const float* t6 = trig + (l * Q_DIM + q) * 6;
            float cp = t6[0], spv = t6[1];
            float ct = t6[2], st  = t6[3];
            float co = t6[4], so  = t6[5];
            float x1 = x * cp - y * spv;
            float y1 = x * spv + y * cp;
            float x2 = x1 * ct + z * st;
            float z2 = -x1 * st + z * ct;
            x = x2 * co - y1 * so;
            y = x2 * so + y1 * co;
            z = z2;
        }
        zout[i] = z;
    }
    __syncthreads();                          // everyone done reading scratch

    // reuse scratch as zbuf[32][16]
#pragma unroll
    for (int i = 0; i < 4; i++) scratch[tid * 4 + i] = zout[i];
    __syncthreads();

    // ---- GEMM2: out[32][512] = z[32][16] @ lw[16][512] + lb ---------------
    const int c0 = tid * 4;                   // four output cols per thread
    ulonglong2 wreg[16];
#pragma unroll
    for (int q = 0; q < 16; q++)
        wreg[q] = *reinterpret_cast<const ulonglong2*>(
            lw + (size_t)q * C_DIM + c0);
    const ulonglong2 bias4 =
        *reinterpret_cast<const ulonglong2*>(lb + c0);

    float* obase = out + (size_t)(blockIdx.x * ROWS_PER_BLOCK) * C_DIM + c0;
    for (int r = 0; r < ROWS_PER_BLOCK; r++) {
        ulonglong2 a = bias4;
#pragma unroll
        for (int q = 0; q < 16; q++) {
            float zv = scratch[r * Q_DIM + q];
            unsigned long long zz = packf2(zv, zv);
            a.x = ffma2(zz, wreg[q].x, a.x);
            a.y = ffma2(zz, wreg[q].y, a.y);
        }
        *reinterpret_cast<ulonglong2*>(obase + (size_t)r * C_DIM) = a;
    }
}

extern "C" void kernel_launch(void* const* d_in, const int* in_sizes, int n_in,
                              void* d_out, int out_size) {
    const float* features = (const float*)d_in[0];
    const float* pw       = (const float*)d_in[1];
    const float* pb       = (const float*)d_in[2];
    const float* vqcw     = (const float*)d_in[3];
    const float* lw       = (const float*)d_in[4];
    const float* lb       = (const float*)d_in[5];
    float* out            = (float*)d_out;

    vqc_router_fused<<<NUM_BLOCKS, THREADS, SMEM_BYTES>>>(
        features, pw, pb, vqcw, lw, lb, out);
}

// round 12
// speedup vs baseline: 2.1604x; 1.1172x over previous
#include <cuda_runtime.h>
#include <cstdint>

#define PI_F 3.14159265358979323846f

// ---------------------------------------------------------------------------
// Fixed shapes:
//   features      [8192, 4096] f32      projection_w  [16, 4096] f32
//   projection_b  [16]         f32      vqc_weights   [24, 16, 3] f32
//   linear_w      [16, 512]    f32      linear_b      [512] f32
//   out           [8192, 512]  f32
// ---------------------------------------------------------------------------
constexpr int B_ROWS  = 8192;
constexpr int D_DIM   = 4096;
constexpr int Q_DIM   = 16;
constexpr int L_LAY   = 24;
constexpr int C_DIM   = 512;

constexpr int ROWS_PER_BLOCK = 32;
constexpr int THREADS        = 128;                       // 4 warps
constexpr int NUM_BLOCKS     = B_ROWS / ROWS_PER_BLOCK;   // 256 -> 2 blocks/SM

constexpr int CHUNK_K = 128;                 // k per pipeline stage
constexpr int NCHUNK  = D_DIM / CHUNK_K;     // 32
constexpr int NSUB    = 4;                   // 32-k subspans per chunk
constexpr int NSTAGES = 3;

constexpr int WSTAGE_FLOATS = Q_DIM * CHUNK_K;            // 2048 (8 KB)
constexpr int FSTAGE_FLOATS = ROWS_PER_BLOCK * CHUNK_K;   // 4096 (16 KB)
constexpr int STAGE_FLOATS  = WSTAGE_FLOATS + FSTAGE_FLOATS;  // 6144

// smem: 3 stages = 18432 floats (72 KB). The post-loop region (partials
// scratch 8192 + trig 2304 = 10496 floats) is OVERLAID on the stages.
constexpr int SMEM_FLOATS = NSTAGES * STAGE_FLOATS;       // 18432
constexpr int SMEM_BYTES  = SMEM_FLOATS * 4;              // 73728
constexpr int SCRATCH_FLOATS = ROWS_PER_BLOCK * Q_DIM * 16;   // 8192

// ---- packed fp32x2 helpers (B300 double-rate fp32 path) -------------------
__device__ __forceinline__ unsigned long long ffma2(unsigned long long a,
                                                    unsigned long long b,
                                                    unsigned long long c) {
    unsigned long long d;
    asm("fma.rn.f32x2 %0, %1, %2, %3;" : "=l"(d) : "l"(a), "l"(b), "l"(c));
    return d;
}
__device__ __forceinline__ float f2lo(unsigned long long v) {
    return __uint_as_float((unsigned)(v & 0xffffffffull));
}
__device__ __forceinline__ float f2hi(unsigned long long v) {
    return __uint_as_float((unsigned)(v >> 32));
}
__device__ __forceinline__ unsigned long long packf2(float lo, float hi) {
    unsigned long long d;
    asm("mov.b64 %0, {%1, %2};" : "=l"(d)
        : "r"(__float_as_uint(lo)), "r"(__float_as_uint(hi)));
    return d;
}

__device__ __forceinline__ void cp_async16(unsigned int dst_smem,
                                           const void* src) {
    asm volatile("cp.async.cg.shared.global [%0], [%1], 16;"
                 :: "r"(dst_smem), "l"(src) : "memory");
}
__device__ __forceinline__ void cp_commit() {
    asm volatile("cp.async.commit_group;" ::: "memory");
}
__device__ __forceinline__ void cp_wait1() {
    asm volatile("cp.async.wait_group 1;" ::: "memory");
}
__device__ __forceinline__ void cp_wait0() {
    asm volatile("cp.async.wait_group 0;" ::: "memory");
}

__global__ void __launch_bounds__(THREADS, 2)
vqc_router_fused(const float* __restrict__ features,
                 const float* __restrict__ pw,
                 const float* __restrict__ pb,
                 const float* __restrict__ vqcw,
                 const float* __restrict__ lw,
                 const float* __restrict__ lb,
                 float* __restrict__ out)
{
    extern __shared__ float smem[];
    float* scratch = smem;                    // overlay: 8192 floats
    float* trig    = smem + SCRATCH_FLOATS;   // overlay: 2304 floats

    const int tid  = threadIdx.x;
    const int lane = tid & 31;
    const int warp = tid >> 5;                // 0..3
    const int s    = lane & 15;               // k-pair slice within 32-k subspan
    const int rg   = warp * 2 + (lane >> 4);  // row-group 0..7 (4 rows each)
    const int rg4  = rg * 4;
    const int brow0 = blockIdx.x * ROWS_PER_BLOCK;

    const unsigned int smem_u32 =
        (unsigned int)__cvta_generic_to_shared(smem);

    // ---- stage loader: chunk c -> stage st (weights 8 KB + features 16 KB)
    auto stage_load = [&](int c, int st) {
        const unsigned int sb = smem_u32 + (unsigned int)(st * STAGE_FLOATS) * 4u;
        // weights: 512 x 16 B segments
#pragma unroll
        for (int i = 0; i < 4; i++) {
            int seg = tid + THREADS * i;          // 0..511
            int q   = seg >> 5;
            int off = (seg & 31) * 4;
            cp_async16(sb + (unsigned int)(q * CHUNK_K + off) * 4u,
                       pw + (size_t)q * D_DIM + c * CHUNK_K + off);
        }
        // features: 1024 x 16 B segments
#pragma unroll
        for (int i = 0; i < 8; i++) {
            int seg = tid + THREADS * i;          // 0..1023
            int row = seg >> 5;
            int off = (seg & 31) * 4;
            cp_async16(sb + (unsigned int)(WSTAGE_FLOATS + row * CHUNK_K + off) * 4u,
                       features + (size_t)(brow0 + row) * D_DIM
                                + c * CHUNK_K + off);
        }
    };

    // ---- pipeline prologue: stages 0,1 in flight --------------------------
    stage_load(0, 0); cp_commit();
    stage_load(1, 1); cp_commit();

    unsigned long long acc[4][16];
#pragma unroll
    for (int r = 0; r < 4; r++)
#pragma unroll
        for (int q = 0; q < 16; q++) acc[r][q] = 0ull;

    // ---- main loop: ONE barrier per chunk, 3-stage ring -------------------
    int st = 0;                                // = c % 3
    for (int c = 0; c < NCHUNK; c++) {
        cp_wait1();            // chunk c's group complete (<=1 outstanding)
        __syncthreads();       // visibility + all warps done with chunk c-1

        // issue chunk c+2 into stage (c+2)%3 == stage consumed at iter c-1
        if (c + 2 < NCHUNK) {
            int st2 = st + 2; if (st2 >= NSTAGES) st2 -= NSTAGES;
            stage_load(c + 2, st2);
        }
        cp_commit();           // uniform group count (empty groups at tail)

        const float* wst = smem + st * STAGE_FLOATS;
        const float* fst = wst + WSTAGE_FLOATS;

#pragma unroll
        for (int sub = 0; sub < NSUB; sub++) {
            unsigned long long f[4];
#pragma unroll
            for (int r = 0; r < 4; r++)
                f[r] = *reinterpret_cast<const unsigned long long*>(
                    fst + (rg4 + r) * CHUNK_K + sub * 32 + 2 * s);
#pragma unroll
            for (int h = 0; h < 2; h++) {
                unsigned long long w[8];
#pragma unroll
                for (int j = 0; j < 8; j++)
                    w[j] = *reinterpret_cast<const unsigned long long*>(
                        wst + (h * 8 + j) * CHUNK_K + sub * 32 + 2 * s);
#pragma unroll
                for (int j = 0; j < 8; j++)
#pragma unroll
                    for (int r = 0; r < 4; r++)
                        acc[r][h * 8 + j] =
                            ffma2(f[r], w[j], acc[r][h * 8 + j]);
            }
        }

        if (++st == NSTAGES) st = 0;
    }
    cp_wait0();
    __syncthreads();           // stages fully consumed; overlay region free

    // ---- write k-split partials + compute trig (disjoint overlay regions) -
#pragma unroll
    for (int j = 0; j < 4; j++)
#pragma unroll
        for (int q = 0; q < 16; q++)
            scratch[((rg4 + j) * Q_DIM + q) * 16 + s] =
                f2lo(acc[j][q]) + f2hi(acc[j][q]);

    for (int i = tid; i < L_LAY * Q_DIM * 3; i += THREADS) {
        float sv, cv;
        sincosf(vqcw[i], &sv, &cv);
        int l   = i / (Q_DIM * 3);
        int rem = i - l * (Q_DIM * 3);
        int q   = rem / 3;
        int p   = rem - q * 3;
        trig[(l * Q_DIM + q) * 6 + 2 * p + 0] = cv;
        trig[(l * Q_DIM + q) * 6 + 2 * p + 1] = sv;
    }
    __syncthreads();

    // ---- reduce 16 partials, tanh, VQC (4 states per thread) --------------
    float zout[4];
#pragma unroll
    for (int i = 0; i < 4; i++) {
        const int idx = tid * 4 + i;          // 0..511
        const int q   = idx & 15;
        const float4* p4 = reinterpret_cast<const float4*>(scratch + idx * 16);
        float4 a0 = p4[0], a1 = p4[1], a2 = p4[2], a3 = p4[3];
        float p = ((a0.x + a0.y) + (a0.z + a0.w))
                + ((a1.x + a1.y) + (a1.z + a1.w))
                + ((a2.x + a2.y) + (a2.z + a2.w))
                + ((a3.x + a3.y) + (a3.z + a3.w)) + pb[q];

        float ang = PI_F * tanhf(p);
        float x, z;
        sincosf(ang, &x, &z);                 // x = sin, z = cos
        float y = 0.0f;
#pragma unroll
        for (int l = 0; l < L_LAY; l++) {
            const float* t6 = trig + (l * Q_DIM + q) * 6;
            float cp = t6[0], spv = t6[1];
            float ct = t6[2], stt = t6[3];
            float co = t6[4], so  = t6[5];
            float x1 = x * cp - y * spv;
            float y1 = x * spv + y * cp;
            float x2 = x1 * ct + z * stt;
            float z2 = -x1 * stt + z * ct;
            x = x2 * co - y1 * so;
            y = x2 * so + y1 * co;
            z = z2;
        }
        zout[i] = z;
    }
    __syncthreads();                          // everyone done reading scratch

    // reuse scratch as zbuf[32][16]
#pragma unroll
    for (int i = 0; i < 4; i++) scratch[tid * 4 + i] = zout[i];
    __syncthreads();

    // ---- GEMM2: out[32][512] = z[32][16] @ lw[16][512] + lb ---------------
    const int c0 = tid * 4;                   // four output cols per thread
    ulonglong2 wreg[16];
#pragma unroll
    for (int q = 0; q < 16; q++)
        wreg[q] = *reinterpret_cast<const ulonglong2*>(
            lw + (size_t)q * C_DIM + c0);
    const ulonglong2 bias4 =
        *reinterpret_cast<const ulonglong2*>(lb + c0);

    float* obase = out + (size_t)brow0 * C_DIM + c0;
    for (int r = 0; r < ROWS_PER_BLOCK; r++) {
        ulonglong2 a = bias4;
#pragma unroll
        for (int q = 0; q < 16; q++) {
            float zv = scratch[r * Q_DIM + q];
            unsigned long long zz = packf2(zv, zv);
            a.x = ffma2(zz, wreg[q].x, a.x);
            a.y = ffma2(zz, wreg[q].y, a.y);
        }
        *reinterpret_cast<ulonglong2*>(obase + (size_t)r * C_DIM) = a;
    }
}

extern "C" void kernel_launch(void* const* d_in, const int* in_sizes, int n_in,
                              void* d_out, int out_size) {
    const float* features = (const float*)d_in[0];
    const float* pw       = (const float*)d_in[1];
    const float* pb       = (const float*)d_in[2];
    const float* vqcw     = (const float*)d_in[3];
    const float* lw       = (const float*)d_in[4];
    const float* lb       = (const float*)d_in[5];
    float* out            = (float*)d_out;

    cudaFuncSetAttribute(vqc_router_fused,
                         cudaFuncAttributeMaxDynamicSharedMemorySize,
                         SMEM_BYTES);
    vqc_router_fused<<<NUM_BLOCKS, THREADS, SMEM_BYTES>>>(
        features, pw, pb, vqcw, lw, lb, out);
}